// round 3
// baseline (speedup 1.0000x reference)
#include <cuda_runtime.h>
#include <cuda_bf16.h>
#include <cstdint>

// LSTM: B=8192, T=128, IN=32, H=64 (4H=256 gate rows), OUT=8.
// Inputs (metadata order): 0:x[B,T,32] 1:W_ih[256,32] 2:W_hh[256,64]
//                          3:b_ih[256] 4:b_hh[256] 5:W_fc[8,64] 6:b_fc[8]
// Output: [B,8] fp32.

#define B_TOT   8192
#define T_LEN   128
#define IN_SZ   32
#define HID     64
#define GATES   256     // 4*HID
#define WARPS   8
#define EPW     8       // batch elements per warp (4 f32x2 pairs)
#define CTA_E   (WARPS*EPW)   // 64 elements per CTA
#define NCTA    (B_TOT/CTA_E) // 128

typedef unsigned long long ull;

// Pre-transposed weights (prep kernel output). Layout (float index):
//   Wq[j*256 + (k>>2)*128 + l*4 + (k&3)] = W[(k*32+l)*RowLen + j]
// so lane l at column j loads two conflict-free float4s:
//   float4 idx j*64 + l  (k=0..3)  and  j*64 + 32 + l  (k=4..7)
__device__ float g_Whh[HID * GATES];   // 16384 floats
__device__ float g_Wih[IN_SZ * GATES]; //  8192 floats

// ---------------- packed f32x2 helpers ----------------
__device__ __forceinline__ ull pack2(float a, float b) {
    ull r;
    asm("mov.b64 %0, {%1, %2};" : "=l"(r) : "f"(a), "f"(b));
    return r;
}
__device__ __forceinline__ void unpack2(ull v, float& a, float& b) {
    asm("mov.b64 {%0, %1}, %2;" : "=f"(a), "=f"(b) : "l"(v));
}
__device__ __forceinline__ ull ffma2(ull a, ull b, ull c) {
    ull d;
    asm("fma.rn.f32x2 %0, %1, %2, %3;" : "=l"(d) : "l"(a), "l"(b), "l"(c));
    return d;
}

// ---------------- activations (high accuracy, MUFU-based) ----------------
__device__ __forceinline__ float sigmoidf_(float x) {
    float e = __expf(-x);                 // FMUL + MUFU.EX2
    return __fdividef(1.0f, 1.0f + e);    // MUFU.RCP
}
__device__ __forceinline__ float tanhf_(float x) {
    x = fminf(fmaxf(x, -15.0f), 15.0f);   // keep exp finite
    float e = __expf(-2.0f * x);
    float r = __fdividef(1.0f, 1.0f + e);
    return fmaf(-2.0f * e, r, 1.0f);      // (1-e)/(1+e), no cancellation blowup
}

// ---------------- weight prep ----------------
__global__ void lstm_prep_kernel(const float* __restrict__ W_ih,
                                 const float* __restrict__ W_hh) {
    int i = blockIdx.x * blockDim.x + threadIdx.x;  // 0..16383
    {
        int j = i >> 8;            // 0..63
        int r = i & 255;
        int khi = r >> 7;
        int low = r & 127;
        int l = low >> 2;
        int k = khi * 4 + (low & 3);
        g_Whh[i] = W_hh[(k * 32 + l) * HID + j];
    }
    if (i < IN_SZ * GATES) {
        int j = i >> 8;            // 0..31
        int r = i & 255;
        int khi = r >> 7;
        int low = r & 127;
        int l = low >> 2;
        int k = khi * 4 + (low & 3);
        g_Wih[i] = W_ih[(k * 32 + l) * IN_SZ + j];
    }
}

// one GEMM column: 8 dup'd weights x 4 element-pairs -> 32 FFMA2
__device__ __forceinline__ void gemm_col(ull acc[8][4], float4 wa, float4 wb,
                                         ull h0, ull h1, ull h2, ull h3) {
    ull hh[4] = {h0, h1, h2, h3};
    float wk[8] = {wa.x, wa.y, wa.z, wa.w, wb.x, wb.y, wb.z, wb.w};
#pragma unroll
    for (int k = 0; k < 8; k++) {
        ull wp = pack2(wk[k], wk[k]);
#pragma unroll
        for (int p = 0; p < 4; p++) acc[k][p] = ffma2(wp, hh[p], acc[k][p]);
    }
}

// ---------------- main LSTM kernel ----------------
__global__ __launch_bounds__(256, 1)
void lstm_main_kernel(const float* __restrict__ x,
                      const float* __restrict__ b_ih,
                      const float* __restrict__ b_hh,
                      const float* __restrict__ W_fc,
                      const float* __restrict__ b_fc,
                      float* __restrict__ out) {
    extern __shared__ float smem[];
    float* sWhh = smem;                       // 16384 floats (64 KB)
    float* sWih = smem + HID * GATES;         //  8192 floats (32 KB)
    ull*   h_all = (ull*)(smem + HID * GATES + IN_SZ * GATES);  // 8 warps * 256 ull
    ull*   x_all = h_all + WARPS * (HID * 4);                   // 8 warps * 128 ull

    // stage weights: global (prepped) -> shared
    {
        const float4* s0 = (const float4*)g_Whh;
        float4* d0 = (float4*)sWhh;
        for (int i = threadIdx.x; i < (HID * GATES) / 4; i += 256) d0[i] = s0[i];
        const float4* s1 = (const float4*)g_Wih;
        float4* d1 = (float4*)sWih;
        for (int i = threadIdx.x; i < (IN_SZ * GATES) / 4; i += 256) d1[i] = s1[i];
    }
    __syncthreads();

    const int w = threadIdx.x >> 5;
    const int l = threadIdx.x & 31;
    ull* hsm = h_all + w * (HID * 4);   // [64 j][4 pair] f32x2
    ull* xsm = x_all + w * (IN_SZ * 4); // [32 j][4 pair] f32x2
    const int ebase = blockIdx.x * CTA_E + w * EPW;

    // bias (b_ih + b_hh), one scalar per gate-row group k
    float bk[8];
#pragma unroll
    for (int k = 0; k < 8; k++) {
        int r = k * 32 + l;
        bk[k] = b_ih[r] + b_hh[r];
    }

    // state: c packed per (half, pair); h lives in hsm
    ull c[2][4];
#pragma unroll
    for (int hf = 0; hf < 2; hf++)
#pragma unroll
        for (int p = 0; p < 4; p++) c[hf][p] = 0ull;
    for (int i = l; i < HID * 4; i += 32) hsm[i] = 0ull;
    __syncwarp();

    const float* xb = x + (size_t)ebase * (T_LEN * IN_SZ) + l;
    float xv[EPW];
#pragma unroll
    for (int e = 0; e < EPW; e++) xv[e] = xb[e * (T_LEN * IN_SZ)];  // t=0

    const float4* Wh4 = (const float4*)sWhh;
    const float4* Wi4 = (const float4*)sWih;

    for (int t = 0; t < T_LEN; t++) {
        // stage x[:, t, :] into xsm (j=lane, pair=e>>1, comp=e&1)
        float* xsf = (float*)xsm;
#pragma unroll
        for (int e = 0; e < EPW; e++)
            xsf[l * 8 + (e >> 1) * 2 + (e & 1)] = xv[e];
        __syncwarp();

        // prefetch next timestep's x (latency hidden behind GEMMs)
        if (t < T_LEN - 1) {
#pragma unroll
            for (int e = 0; e < EPW; e++)
                xv[e] = xb[e * (T_LEN * IN_SZ) + (t + 1) * IN_SZ];
        }

        // init accumulators with bias (both halves of each pair)
        ull acc[8][4];
#pragma unroll
        for (int k = 0; k < 8; k++) {
            ull bp = pack2(bk[k], bk[k]);
#pragma unroll
            for (int p = 0; p < 4; p++) acc[k][p] = bp;
        }

        // input GEMM: j over 32 input features
#pragma unroll 4
        for (int j = 0; j < IN_SZ; j++) {
            ull h0 = xsm[j * 4 + 0], h1 = xsm[j * 4 + 1];
            ull h2 = xsm[j * 4 + 2], h3 = xsm[j * 4 + 3];
            float4 wa = Wi4[j * 64 + l];
            float4 wb = Wi4[j * 64 + 32 + l];
            gemm_col(acc, wa, wb, h0, h1, h2, h3);
        }

        // recurrent GEMM: j over 64 hidden units
#pragma unroll 4
        for (int j = 0; j < HID; j++) {
            ull h0 = hsm[j * 4 + 0], h1 = hsm[j * 4 + 1];
            ull h2 = hsm[j * 4 + 2], h3 = hsm[j * 4 + 3];
            float4 wa = Wh4[j * 64 + l];
            float4 wb = Wh4[j * 64 + 32 + l];
            gemm_col(acc, wa, wb, h0, h1, h2, h3);
        }
        __syncwarp();  // all lanes done reading hsm before owners overwrite

        // gates -> state update. Lane l owns hidden indices l (hf=0), l+32 (hf=1).
        // gate k mapping: i:k=hf, f:k=2+hf, g:k=4+hf, o:k=6+hf
#pragma unroll
        for (int hf = 0; hf < 2; hf++) {
#pragma unroll
            for (int p = 0; p < 4; p++) {
                float ia0, ia1, fa0, fa1, ga0, ga1, oa0, oa1, c0, c1;
                unpack2(acc[0 + hf][p], ia0, ia1);
                unpack2(acc[2 + hf][p], fa0, fa1);
                unpack2(acc[4 + hf][p], ga0, ga1);
                unpack2(acc[6 + hf][p], oa0, oa1);
                unpack2(c[hf][p], c0, c1);

                float I0 = sigmoidf_(ia0), F0 = sigmoidf_(fa0);
                float G0 = tanhf_(ga0),    O0 = sigmoidf_(oa0);
                c0 = fmaf(F0, c0, I0 * G0);
                float H0 = O0 * tanhf_(c0);

                float I1 = sigmoidf_(ia1), F1 = sigmoidf_(fa1);
                float G1 = tanhf_(ga1),    O1 = sigmoidf_(oa1);
                c1 = fmaf(F1, c1, I1 * G1);
                float H1 = O1 * tanhf_(c1);

                c[hf][p] = pack2(c0, c1);
                hsm[(l + 32 * hf) * 4 + p] = pack2(H0, H1);
            }
        }
        __syncwarp();  // publish h for next step
    }

    // final FC: out[e][o] = h[e] . W_fc[o] + b_fc[o]
    // 4 lanes per element, 2 outputs per lane
    {
        const float* hs = (const float*)hsm;
        int e = l >> 2;
        int o0 = (l & 3) * 2;
        float s0 = b_fc[o0], s1 = b_fc[o0 + 1];
        const int comp = (e >> 1) * 2 + (e & 1);
#pragma unroll 8
        for (int j = 0; j < HID; j++) {
            float hv = hs[j * 8 + comp];
            s0 = fmaf(hv, W_fc[o0 * HID + j], s0);
            s1 = fmaf(hv, W_fc[(o0 + 1) * HID + j], s1);
        }
        out[(size_t)(ebase + e) * 8 + o0]     = s0;
        out[(size_t)(ebase + e) * 8 + o0 + 1] = s1;
    }
}

extern "C" void kernel_launch(void* const* d_in, const int* in_sizes, int n_in,
                              void* d_out, int out_size) {
    const float* x    = (const float*)d_in[0];
    const float* W_ih = (const float*)d_in[1];
    const float* W_hh = (const float*)d_in[2];
    const float* b_ih = (const float*)d_in[3];
    const float* b_hh = (const float*)d_in[4];
    const float* W_fc = (const float*)d_in[5];
    const float* b_fc = (const float*)d_in[6];
    float* out = (float*)d_out;

    // dynamic smem: weights (96 KB) + h rings (16 KB) + x rings (8 KB)
    const int smem_bytes =
        (HID * GATES + IN_SZ * GATES) * 4 + WARPS * HID * 4 * 8 + WARPS * IN_SZ * 4 * 8;
    cudaFuncSetAttribute(lstm_main_kernel,
                         cudaFuncAttributeMaxDynamicSharedMemorySize, smem_bytes);

    lstm_prep_kernel<<<64, 256>>>(W_ih, W_hh);
    lstm_main_kernel<<<NCTA, 256, smem_bytes>>>(x, b_ih, b_hh, W_fc, b_fc, out);
}